// round 10
// baseline (speedup 1.0000x reference)
#include <cuda_runtime.h>

#define R_ROWS 8192
#define N_FEAT 4096
#define NP1    4097
#define NVEC   1023   // float4 vectors per row body (features s .. s+4091)
#define G      4      // rows per block
#define SETUP_BLOCKS 64

// AoS pack for the scalar peel: (dl, du, bl, bu)
__device__ float4 g_pack[N_FEAT];

// Shift-replicated SoA float4 const arrays: g_dl4[s][i] = dl[s+4i .. s+4i+3].
__device__ float4 g_dl4[4][NVEC];
__device__ float4 g_du4[4][NVEC];
__device__ float4 g_bl4[4][NVEC];
__device__ float4 g_bu4[4][NVEC];

// Producer/consumer handoff state (self-resetting each launch).
__device__ volatile int g_done;   // producers finished (target: SETUP_BLOCKS)
__device__ int g_exit;            // blocks finished (for reset)

// Single fused kernel. Grid 4096. Blocks 0..63 first write the const arrays
// (one item per thread: 64*256 = 4*N_FEAT items), bump g_done; every block
// spins until g_done == SETUP_BLOCKS before reading g_* .
// Main mapping: half = blk/2048 (0=lb,1=ub); within half c = q>>9 (alignment
// class), p = q&511 (group); rows r_g = c + 4*(p*G + g).
__global__ __launch_bounds__(256)
void relu_backsub_fused(const float* __restrict__ lb,
                        const float* __restrict__ ub,
                        const float* __restrict__ wlb,
                        const float* __restrict__ wub,
                        float* __restrict__ out) {
    const int blk = blockIdx.x;
    const int t = threadIdx.x;

    // ---- producer phase: blocks 0..63 build the const arrays ----
    if (blk < SETUP_BLOCKS) {
        const int idx = blk * 256 + t;        // 0 .. 16383
        const int c = idx >> 12;              // 0..3
        const int j = idx & (N_FEAT - 1);     // 0..4095

        const size_t row = (size_t)j * NP1;
        const float* src = (c & 1) ? wub : wlb;
        const size_t col = (c & 2) ? (size_t)N_FEAT : (size_t)j;
        const float v = src[row + col];

        ((float*)g_pack)[4 * j + c] = v;

        float* const dst = (c == 0) ? (float*)g_dl4
                         : (c == 1) ? (float*)g_du4
                         : (c == 2) ? (float*)g_bl4
                                    : (float*)g_bu4;
#pragma unroll
        for (int s = 0; s < 4; ++s) {
            const int rem = j - s;
            if (rem >= 0 && rem < 4 * NVEC)
                dst[s * 4 * NVEC + rem] = v;
        }
        __threadfence();
        __syncthreads();
        if (t == 0) atomicAdd((int*)&g_done, 1);
    }

    // ---- consumer gate: wait for all producers ----
    if (t == 0) {
        while (g_done < SETUP_BLOCKS) { }
    }
    __syncthreads();
    __threadfence();   // order const reads after the flag observation

    // ---- main work ----
    const bool is_ub = (blk >= 2048);
    const int q = is_ub ? (blk - 2048) : blk;
    const int c = q >> 9;          // alignment class
    const int p = q & 511;         // row group

    const int r0 = c + 4 * (p * G);
    const float* __restrict__ xbase = (is_ub ? ub : lb) + (size_t)r0 * NP1;
    float* __restrict__ obase = out + ((size_t)(is_ub ? R_ROWS : 0) + r0) * NP1;
    const size_t rstride = (size_t)4 * NP1;

    const int s = (4 - c) & 3;     // (r0*NP1 + s) % 4 == 0

    const float4* __restrict__ dA = is_ub ? g_du4[s] : g_dl4[s];
    const float4* __restrict__ dB = is_ub ? g_dl4[s] : g_du4[s];
    const float4* __restrict__ bA = is_ub ? g_bu4[s] : g_bl4[s];
    const float4* __restrict__ bB = is_ub ? g_bl4[s] : g_bu4[s];

    float acc[G];
#pragma unroll
    for (int g = 0; g < G; ++g) acc[g] = 0.0f;

    // scalar peel: 4 boundary elements per row
    if (t < 4 * G) {
        const int g = t >> 2;
        const int e = t & 3;
        const int j = (e < s) ? e : (4092 + e);
        const float v = xbase[g * rstride + j];
        const float4 pk = g_pack[j];
        const float da = is_ub ? pk.y : pk.x;
        const float db = is_ub ? pk.x : pk.y;
        const float ba = is_ub ? pk.w : pk.z;
        const float bb = is_ub ? pk.z : pk.w;
        obase[g * rstride + j] = v * ((v >= 0.0f) ? da : db);
        acc[g] = fmaf(v, (v >= 0.0f) ? ba : bb, acc[g]);
    }

    // vector body: load consts once, apply to G rows
    for (int i = t; i < NVEC; i += 256) {
        const int j0 = s + 4 * i;
        const float4 vdA = dA[i];
        const float4 vdB = dB[i];
        const float4 vbA = bA[i];
        const float4 vbB = bB[i];

#pragma unroll
        for (int g = 0; g < G; ++g) {
            const float4 xv =
                *reinterpret_cast<const float4*>(xbase + g * rstride + j0);
            float4 ov;
            ov.x = xv.x * ((xv.x >= 0.0f) ? vdA.x : vdB.x);
            acc[g] = fmaf(xv.x, (xv.x >= 0.0f) ? vbA.x : vbB.x, acc[g]);
            ov.y = xv.y * ((xv.y >= 0.0f) ? vdA.y : vdB.y);
            acc[g] = fmaf(xv.y, (xv.y >= 0.0f) ? vbA.y : vbB.y, acc[g]);
            ov.z = xv.z * ((xv.z >= 0.0f) ? vdA.z : vdB.z);
            acc[g] = fmaf(xv.z, (xv.z >= 0.0f) ? vbA.z : vbB.z, acc[g]);
            ov.w = xv.w * ((xv.w >= 0.0f) ? vdA.w : vdB.w);
            acc[g] = fmaf(xv.w, (xv.w >= 0.0f) ? vbA.w : vbB.w, acc[g]);
            *reinterpret_cast<float4*>(obase + g * rstride + j0) = ov;
        }
    }

    // block reduction: G independent sums
    __shared__ float red[8][G];
#pragma unroll
    for (int g = 0; g < G; ++g) {
#pragma unroll
        for (int off = 16; off > 0; off >>= 1)
            acc[g] += __shfl_down_sync(0xffffffffu, acc[g], off);
    }
    if ((t & 31) == 0) {
#pragma unroll
        for (int g = 0; g < G; ++g) red[t >> 5][g] = acc[g];
    }
    __syncthreads();
    if (t < G) {
        float tot = 0.0f;
#pragma unroll
        for (int w = 0; w < 8; ++w) tot += red[w][t];
        obase[t * rstride + N_FEAT] = tot + xbase[t * rstride + N_FEAT];
    }

    // ---- self-reset for graph replays: last block zeroes the counters ----
    __syncthreads();
    if (t == 0) {
        const int old = atomicAdd(&g_exit, 1);
        if (old == (int)gridDim.x - 1) {
            g_exit = 0;
            *(int*)&g_done = 0;
            __threadfence();
        }
    }
}

extern "C" void kernel_launch(void* const* d_in, const int* in_sizes, int n_in,
                              void* d_out, int out_size) {
    const float* lb  = (const float*)d_in[0];
    const float* ub  = (const float*)d_in[1];
    const float* wlb = (const float*)d_in[2];
    const float* wub = (const float*)d_in[3];
    float* out = (float*)d_out;

    relu_backsub_fused<<<4096, 256>>>(lb, ub, wlb, wub, out);
}

// round 11
// speedup vs baseline: 1.0917x; 1.0917x over previous
#include <cuda_runtime.h>

#define R_ROWS 8192
#define N_FEAT 4096
#define NP1    4097
#define NVEC   1023   // float4 vectors per row body (features s .. s+4091)
#define G      4      // rows per block

// AoS pack for the scalar peel: (dl, du, bl, bu)
__device__ float4 g_pack[N_FEAT];

// Shift-replicated SoA float4 const arrays: g_dl4[s][i] = dl[s+4i .. s+4i+3].
__device__ float4 g_dl4[4][NVEC];
__device__ float4 g_du4[4][NVEC];
__device__ float4 g_bl4[4][NVEC];
__device__ float4 g_bu4[4][NVEC];

// Parallel setup: one thread per (array c, feature j) item.
__global__ __launch_bounds__(128)
void setup_kernel(const float* __restrict__ wlb,
                  const float* __restrict__ wub) {
    const int idx = blockIdx.x * blockDim.x + threadIdx.x;
    if (idx >= 4 * N_FEAT) return;
    const int c = idx >> 12;          // 0..3
    const int j = idx & (N_FEAT - 1); // 0..4095

    const size_t row = (size_t)j * NP1;
    const float* src = (c & 1) ? wub : wlb;
    const size_t col = (c & 2) ? (size_t)N_FEAT : (size_t)j;
    const float v = src[row + col];

    ((float*)g_pack)[4 * j + c] = v;

    float* const dst = (c == 0) ? (float*)g_dl4
                     : (c == 1) ? (float*)g_du4
                     : (c == 2) ? (float*)g_bl4
                                : (float*)g_bu4;
#pragma unroll
    for (int s = 0; s < 4; ++s) {
        const int rem = j - s;
        if (rem >= 0 && rem < 4 * NVEC)
            dst[s * 4 * NVEC + rem] = v;
    }
}

// Block layout: blk in [0, 4096). Half = blk/2048 (0=lb,1=ub).
// Within half: c = shift class (0..3, q>>9), p = group (0..511, q&511).
// Rows handled: r_g = c + 4*(p*G + g), g = 0..G-1 — all share alignment class c.
__global__ __launch_bounds__(256)
void relu_backsub_kernel(const float* __restrict__ lb,
                         const float* __restrict__ ub,
                         float* __restrict__ out) {
    const int blk = blockIdx.x;
    const bool is_ub = (blk >= 2048);
    const int q = is_ub ? (blk - 2048) : blk;
    const int c = q >> 9;          // alignment class
    const int p = q & 511;         // row group

    const int r0 = c + 4 * (p * G);                 // first row of the group
    const float* __restrict__ xbase = (is_ub ? ub : lb) + (size_t)r0 * NP1;
    float* __restrict__ obase = out + ((size_t)(is_ub ? R_ROWS : 0) + r0) * NP1;
    const size_t rstride = (size_t)4 * NP1;         // stride between group rows

    const int s = (4 - c) & 3;                      // (r0*NP1 + s) % 4 == 0

    const float4* __restrict__ dA = is_ub ? g_du4[s] : g_dl4[s];
    const float4* __restrict__ dB = is_ub ? g_dl4[s] : g_du4[s];
    const float4* __restrict__ bA = is_ub ? g_bu4[s] : g_bl4[s];
    const float4* __restrict__ bB = is_ub ? g_bl4[s] : g_bu4[s];

    const int t = threadIdx.x;

    // PDL: this grid's launch/dispatch overlaps setup_kernel's execution.
    cudaGridDependencySynchronize();

    float acc[G];
#pragma unroll
    for (int g = 0; g < G; ++g) acc[g] = 0.0f;

    // ---- scalar peel: 4 boundary elements per row, covers all G rows ----
    if (t < 4 * G) {
        const int g = t >> 2;
        const int e = t & 3;
        const int j = (e < s) ? e : (4092 + e);
        const float v = xbase[g * rstride + j];
        const float4 pk = g_pack[j];
        const float da = is_ub ? pk.y : pk.x;
        const float db = is_ub ? pk.x : pk.y;
        const float ba = is_ub ? pk.w : pk.z;
        const float bb = is_ub ? pk.z : pk.w;
        obase[g * rstride + j] = v * ((v >= 0.0f) ? da : db);
        acc[g] = fmaf(v, (v >= 0.0f) ? ba : bb, acc[g]);
    }

    // ---- vector body: load consts once, apply to G rows ----
    for (int i = t; i < NVEC; i += 256) {
        const int j0 = s + 4 * i;
        const float4 vdA = dA[i];
        const float4 vdB = dB[i];
        const float4 vbA = bA[i];
        const float4 vbB = bB[i];

#pragma unroll
        for (int g = 0; g < G; ++g) {
            const float4 xv =
                *reinterpret_cast<const float4*>(xbase + g * rstride + j0);
            float4 ov;
            ov.x = xv.x * ((xv.x >= 0.0f) ? vdA.x : vdB.x);
            acc[g] = fmaf(xv.x, (xv.x >= 0.0f) ? vbA.x : vbB.x, acc[g]);
            ov.y = xv.y * ((xv.y >= 0.0f) ? vdA.y : vdB.y);
            acc[g] = fmaf(xv.y, (xv.y >= 0.0f) ? vbA.y : vbB.y, acc[g]);
            ov.z = xv.z * ((xv.z >= 0.0f) ? vdA.z : vdB.z);
            acc[g] = fmaf(xv.z, (xv.z >= 0.0f) ? vbA.z : vbB.z, acc[g]);
            ov.w = xv.w * ((xv.w >= 0.0f) ? vdA.w : vdB.w);
            acc[g] = fmaf(xv.w, (xv.w >= 0.0f) ? vbA.w : vbB.w, acc[g]);
            *reinterpret_cast<float4*>(obase + g * rstride + j0) = ov;
        }
    }

    // ---- block reduction: G independent sums ----
    __shared__ float red[8][G];
#pragma unroll
    for (int g = 0; g < G; ++g) {
#pragma unroll
        for (int off = 16; off > 0; off >>= 1)
            acc[g] += __shfl_down_sync(0xffffffffu, acc[g], off);
    }
    if ((t & 31) == 0) {
#pragma unroll
        for (int g = 0; g < G; ++g) red[t >> 5][g] = acc[g];
    }
    __syncthreads();
    if (t < G) {
        float tot = 0.0f;
#pragma unroll
        for (int w = 0; w < 8; ++w) tot += red[w][t];
        // passthrough last element: relu(x) - relu(-x) = x
        obase[t * rstride + N_FEAT] = tot + xbase[t * rstride + N_FEAT];
    }
}

extern "C" void kernel_launch(void* const* d_in, const int* in_sizes, int n_in,
                              void* d_out, int out_size) {
    const float* lb  = (const float*)d_in[0];
    const float* ub  = (const float*)d_in[1];
    const float* wlb = (const float*)d_in[2];
    const float* wub = (const float*)d_in[3];
    float* out = (float*)d_out;

    setup_kernel<<<(4 * N_FEAT + 127) / 128, 128>>>(wlb, wub);

    cudaLaunchConfig_t cfg = {};
    cfg.gridDim = dim3(4096);
    cfg.blockDim = dim3(256);
    cfg.dynamicSmemBytes = 0;
    cfg.stream = 0;
    cudaLaunchAttribute attr[1];
    attr[0].id = cudaLaunchAttributeProgrammaticStreamSerialization;
    attr[0].val.programmaticStreamSerializationAllowed = 1;
    cfg.attrs = attr;
    cfg.numAttrs = 1;
    cudaLaunchKernelEx(&cfg, relu_backsub_kernel, lb, ub, out);
}

// round 12
// speedup vs baseline: 1.0925x; 1.0007x over previous
#include <cuda_runtime.h>

#define R_ROWS 8192
#define N_FEAT 4096
#define NP1    4097
#define NVEC   1023   // float4 vectors per row body (features s .. s+4091)
#define G      4      // rows per block

// AoS pack for the scalar peel: (dl, du, bl, bu)
__device__ float4 g_pack[N_FEAT];

// Shift-replicated SoA float4 const arrays: g_dl4[s][i] = dl[s+4i .. s+4i+3].
__device__ float4 g_dl4[4][NVEC];
__device__ float4 g_du4[4][NVEC];
__device__ float4 g_bl4[4][NVEC];
__device__ float4 g_bu4[4][NVEC];

// Parallel setup: one thread per (array c, feature j) item.
__global__ __launch_bounds__(128)
void setup_kernel(const float* __restrict__ wlb,
                  const float* __restrict__ wub) {
    const int idx = blockIdx.x * blockDim.x + threadIdx.x;
    if (idx >= 4 * N_FEAT) return;
    const int c = idx >> 12;          // 0..3
    const int j = idx & (N_FEAT - 1); // 0..4095

    const size_t row = (size_t)j * NP1;
    const float* src = (c & 1) ? wub : wlb;
    const size_t col = (c & 2) ? (size_t)N_FEAT : (size_t)j;
    const float v = src[row + col];

    ((float*)g_pack)[4 * j + c] = v;

    float* const dst = (c == 0) ? (float*)g_dl4
                     : (c == 1) ? (float*)g_du4
                     : (c == 2) ? (float*)g_bl4
                                : (float*)g_bu4;
#pragma unroll
    for (int s = 0; s < 4; ++s) {
        const int rem = j - s;
        if (rem >= 0 && rem < 4 * NVEC)
            dst[s * 4 * NVEC + rem] = v;
    }
}

// Block layout: blk in [0, 4096). Half = blk/2048 (0=lb,1=ub).
// Within half: c = shift class (0..3, q>>9), p = group (0..511, q&511).
// Rows handled: r_g = c + 4*(p*G + g), g = 0..G-1 — all share alignment class c.
__global__ __launch_bounds__(256)
void relu_backsub_kernel(const float* __restrict__ lb,
                         const float* __restrict__ ub,
                         float* __restrict__ out) {
    const int blk = blockIdx.x;
    const bool is_ub = (blk >= 2048);
    const int q = is_ub ? (blk - 2048) : blk;
    const int c = q >> 9;          // alignment class
    const int p = q & 511;         // row group

    const int r0 = c + 4 * (p * G);                 // first row of the group
    const float* __restrict__ xbase = (is_ub ? ub : lb) + (size_t)r0 * NP1;
    float* __restrict__ obase = out + ((size_t)(is_ub ? R_ROWS : 0) + r0) * NP1;
    const size_t rstride = (size_t)4 * NP1;         // stride between group rows

    const int s = (4 - c) & 3;                      // (r0*NP1 + s) % 4 == 0

    const float4* __restrict__ dA = is_ub ? g_du4[s] : g_dl4[s];
    const float4* __restrict__ dB = is_ub ? g_dl4[s] : g_du4[s];
    const float4* __restrict__ bA = is_ub ? g_bu4[s] : g_bl4[s];
    const float4* __restrict__ bB = is_ub ? g_bl4[s] : g_bu4[s];

    const int t = threadIdx.x;

    // PDL: this grid's launch/dispatch overlaps setup_kernel's execution.
    cudaGridDependencySynchronize();

    float acc[G];
#pragma unroll
    for (int g = 0; g < G; ++g) acc[g] = 0.0f;

    // ---- scalar peel: 4 boundary elements per row, covers all G rows ----
    if (t < 4 * G) {
        const int g = t >> 2;
        const int e = t & 3;
        const int j = (e < s) ? e : (4092 + e);
        const float v = xbase[g * rstride + j];
        const float4 pk = g_pack[j];
        const float da = is_ub ? pk.y : pk.x;
        const float db = is_ub ? pk.x : pk.y;
        const float ba = is_ub ? pk.w : pk.z;
        const float bb = is_ub ? pk.z : pk.w;
        obase[g * rstride + j] = v * ((v >= 0.0f) ? da : db);
        acc[g] = fmaf(v, (v >= 0.0f) ? ba : bb, acc[g]);
    }

    // ---- vector body: batch all row loads first (MLP), then compute+store ----
    for (int i = t; i < NVEC; i += 256) {
        const int j0 = s + 4 * i;

        // front-batched loads: 4 row float4s + 4 const float4s in flight
        float4 xv[G];
#pragma unroll
        for (int g = 0; g < G; ++g)
            xv[g] = *reinterpret_cast<const float4*>(xbase + g * rstride + j0);

        const float4 vdA = dA[i];
        const float4 vdB = dB[i];
        const float4 vbA = bA[i];
        const float4 vbB = bB[i];

#pragma unroll
        for (int g = 0; g < G; ++g) {
            float4 ov;
            ov.x = xv[g].x * ((xv[g].x >= 0.0f) ? vdA.x : vdB.x);
            acc[g] = fmaf(xv[g].x, (xv[g].x >= 0.0f) ? vbA.x : vbB.x, acc[g]);
            ov.y = xv[g].y * ((xv[g].y >= 0.0f) ? vdA.y : vdB.y);
            acc[g] = fmaf(xv[g].y, (xv[g].y >= 0.0f) ? vbA.y : vbB.y, acc[g]);
            ov.z = xv[g].z * ((xv[g].z >= 0.0f) ? vdA.z : vdB.z);
            acc[g] = fmaf(xv[g].z, (xv[g].z >= 0.0f) ? vbA.z : vbB.z, acc[g]);
            ov.w = xv[g].w * ((xv[g].w >= 0.0f) ? vdA.w : vdB.w);
            acc[g] = fmaf(xv[g].w, (xv[g].w >= 0.0f) ? vbA.w : vbB.w, acc[g]);
            *reinterpret_cast<float4*>(obase + g * rstride + j0) = ov;
        }
    }

    // ---- block reduction: G independent sums ----
    __shared__ float red[8][G];
#pragma unroll
    for (int g = 0; g < G; ++g) {
#pragma unroll
        for (int off = 16; off > 0; off >>= 1)
            acc[g] += __shfl_down_sync(0xffffffffu, acc[g], off);
    }
    if ((t & 31) == 0) {
#pragma unroll
        for (int g = 0; g < G; ++g) red[t >> 5][g] = acc[g];
    }
    __syncthreads();
    if (t < G) {
        float tot = 0.0f;
#pragma unroll
        for (int w = 0; w < 8; ++w) tot += red[w][t];
        // passthrough last element: relu(x) - relu(-x) = x
        obase[t * rstride + N_FEAT] = tot + xbase[t * rstride + N_FEAT];
    }
}

extern "C" void kernel_launch(void* const* d_in, const int* in_sizes, int n_in,
                              void* d_out, int out_size) {
    const float* lb  = (const float*)d_in[0];
    const float* ub  = (const float*)d_in[1];
    const float* wlb = (const float*)d_in[2];
    const float* wub = (const float*)d_in[3];
    float* out = (float*)d_out;

    setup_kernel<<<(4 * N_FEAT + 127) / 128, 128>>>(wlb, wub);

    cudaLaunchConfig_t cfg = {};
    cfg.gridDim = dim3(4096);
    cfg.blockDim = dim3(256);
    cfg.dynamicSmemBytes = 0;
    cfg.stream = 0;
    cudaLaunchAttribute attr[1];
    attr[0].id = cudaLaunchAttributeProgrammaticStreamSerialization;
    attr[0].val.programmaticStreamSerializationAllowed = 1;
    cfg.attrs = attr;
    cfg.numAttrs = 1;
    cudaLaunchKernelEx(&cfg, relu_backsub_kernel, lb, ub, out);
}